// round 16
// baseline (speedup 1.0000x reference)
#include <cuda_runtime.h>
#include <cuda_fp16.h>
#include <math.h>
#include <stdint.h>

#define NROWS 262144
#define C     256
#define NGR   2048
#define NPG   128
#define H     8
#define DH    32
#define EPS   1e-5f
#define ATT_SCALE 0.1767766952966369f   /* 1/sqrt(32) */
#define NMB   2048                      /* m-blocks of 128 rows */

/* ---------------- device scratch ---------------- */
__device__ __half g_h1f[(size_t)NROWS * C];        /* 134 MB */
__device__ __half g_W1f[C * C];
__device__ __half g_A16[16 * C];                   /* rows 0-7 Ak[h], 8-15 Av[h] */
__device__ float g_fin[(size_t)NROWS * 16];        /* 16.8 MB */
__device__ float g_psum[(size_t)C * NMB];
__device__ float g_psq [(size_t)C * NMB];
__device__ float g_bnA[C], g_bnB[C];
__device__ float g_ckk[H], g_cvv[H];
__device__ float g_cb;

/* ---------------- helpers ---------------- */
__device__ __forceinline__ uint32_t smem_u32(const void* p) {
    uint32_t a;
    asm("{ .reg .u64 t; cvta.to.shared.u64 t, %1; cvt.u32.u64 %0, t; }"
        : "=r"(a) : "l"(p));
    return a;
}
__device__ __forceinline__ void ldm_x4(uint32_t addr, uint32_t* r) {
    asm volatile("ldmatrix.sync.aligned.m8n8.x4.shared.b16 {%0,%1,%2,%3}, [%4];"
                 : "=r"(r[0]), "=r"(r[1]), "=r"(r[2]), "=r"(r[3]) : "r"(addr));
}
__device__ __forceinline__ void mma_f16(float* d, const uint32_t* a,
                                        uint32_t b0, uint32_t b1) {
    asm volatile(
        "mma.sync.aligned.m16n8k16.row.col.f32.f16.f16.f32 "
        "{%0,%1,%2,%3}, {%4,%5,%6,%7}, {%8,%9}, {%0,%1,%2,%3};"
        : "+f"(d[0]), "+f"(d[1]), "+f"(d[2]), "+f"(d[3])
        : "r"(a[0]), "r"(a[1]), "r"(a[2]), "r"(a[3]), "r"(b0), "r"(b1));
}
__device__ __forceinline__ void cp_async16(uint32_t dst, const void* src) {
    asm volatile("cp.async.cg.shared.global [%0], [%1], 16;"
                 :: "r"(dst), "l"(src) : "memory");
}
#define CP_COMMIT() asm volatile("cp.async.commit_group;" ::: "memory")
#define CP_WAIT0()  asm volatile("cp.async.wait_group 0;" ::: "memory")
#define CP_WAIT1()  asm volatile("cp.async.wait_group 1;" ::: "memory")

/* ================= prep: W1 fp16 (blocks 0-63) + per-head folds (64-71) ===== */
__global__ void prep_kernel(const float* __restrict__ W1,
                            const float* __restrict__ Wq, const float* __restrict__ bq,
                            const float* __restrict__ Wk, const float* __restrict__ bk,
                            const float* __restrict__ Wv, const float* __restrict__ bv,
                            const float* __restrict__ W2, const float* __restrict__ b2,
                            const float* __restrict__ Wo, const float* __restrict__ bo,
                            const float* __restrict__ Wr, const float* __restrict__ br) {
    int t = threadIdx.x, b = blockIdx.x;
    if (b < 64) {
        int base = b * 1024;
#pragma unroll
        for (int k = 0; k < 4; k++) {
            int i = base + t + k * 256;
            g_W1f[i] = __float2half_rn(W1[i]);
        }
        return;
    }
    int h = b - 64;
    int wid = t >> 5, lane = t & 31;
    __shared__ float qv[DH], uu[DH];
    __shared__ float skq[256], svu[256], red[256], red2[256];

    if (h == 0) {
        red[t] = Wr[t] * bo[t];
        __syncthreads();
        for (int off = 128; off; off >>= 1) {
            if (t < off) red[t] += red[t + off];
            __syncthreads();
        }
        if (t == 0) g_cb = red[0] + br[0];
        __syncthreads();
    }

#pragma unroll
    for (int r8i = 0; r8i < 8; r8i++) {
        int rr = wid * 8 + r8i;
        float s = 0.f;
        if (rr < DH) {
            int row = h * DH + rr;
#pragma unroll
            for (int j = 0; j < 8; j++) s += Wq[row * C + lane + j * 32];
        } else {
            int e = h * DH + (rr - DH);
#pragma unroll
            for (int j = 0; j < 8; j++) {
                int c = lane + j * 32;
                s += Wr[c] * Wo[c * C + e];
            }
        }
#pragma unroll
        for (int o = 16; o; o >>= 1) s += __shfl_xor_sync(0xffffffffu, s, o);
        if (lane == 0) {
            if (rr < DH) qv[rr] = s + bq[h * DH + rr];
            else uu[rr - DH] = s;
        }
    }
    __syncthreads();

    float s = 0.f, s2 = 0.f;
#pragma unroll 8
    for (int d = 0; d < DH; d++) {
        s  += Wk[(h * DH + d) * C + t] * qv[d];
        s2 += uu[d] * Wv[(h * DH + d) * C + t];
    }
    skq[t] = s * ATT_SCALE;
    svu[t] = s2;
    __syncthreads();
    float sk = 0.f, sv = 0.f;
#pragma unroll 8
    for (int a = 0; a < C; a++) {
        float w2 = W2[a * C + t];
        sk += skq[a] * w2;
        sv += svu[a] * w2;
    }
    g_A16[h * C + t]       = __float2half_rn(sk);
    g_A16[(8 + h) * C + t] = __float2half_rn(sv);
    float ckp = skq[t] * b2[t];
    float cvp = svu[t] * b2[t];
    if (t < DH) {
        ckp += bk[h * DH + t] * qv[t] * ATT_SCALE;
        cvp += uu[t] * bv[h * DH + t];
    }
    red[t] = ckp; red2[t] = cvp;
    __syncthreads();
    for (int off = 128; off; off >>= 1) {
        if (t < off) { red[t] += red[t + off]; red2[t] += red2[t + off]; }
        __syncthreads();
    }
    if (t == 0) { g_ckk[h] = red[0]; g_cvv[h] = red2[0]; }
}

/* ================= GEMM1 (exact R7 166us version) ========================= */
#define A_STRIDE_B 80
#define B_STRIDE_B 80
#define A_BYTES (128 * A_STRIDE_B)
#define B_BYTES (256 * B_STRIDE_B)
#define STAGE_BYTES (A_BYTES + B_BYTES)
#define NSTAGE 3
#define STG_STRIDE 264
#define SMEM_DYN (NSTAGE * STAGE_BYTES)

__global__ __launch_bounds__(512, 1)
void gemm1_mma(const float* __restrict__ x, const float* __restrict__ b1) {
    extern __shared__ char sm[];
    __shared__ float sbias[256];
    __shared__ float colsum[4][256], colsq[4][256];

    int tid = threadIdx.x;
    int wid = tid >> 5, lane = tid & 31;
    int wm = wid >> 2, wn = wid & 3;
    int mb = blockIdx.x;
    uint32_t smb = smem_u32(sm);

    if (tid < 256) sbias[tid] = b1[tid];

    const float* xt = x + (size_t)mb * 128 * C;
    int arow = tid >> 2, af8 = tid & 3;

    auto ldA = [&](int kc, float4* pf) {
        const float* p = &xt[(size_t)arow * C + kc * 32 + af8 * 8];
        pf[0] = __ldg((const float4*)p);
        pf[1] = __ldg((const float4*)(p + 4));
    };
    auto stA = [&](int stg, const float4* pf) {
        __half h[8];
        h[0] = __float2half_rn(pf[0].x); h[1] = __float2half_rn(pf[0].y);
        h[2] = __float2half_rn(pf[0].z); h[3] = __float2half_rn(pf[0].w);
        h[4] = __float2half_rn(pf[1].x); h[5] = __float2half_rn(pf[1].y);
        h[6] = __float2half_rn(pf[1].z); h[7] = __float2half_rn(pf[1].w);
        *(uint4*)(sm + stg * STAGE_BYTES + arow * A_STRIDE_B + af8 * 16) = *(uint4*)h;
    };
    auto cpB = [&](int kc, int stg) {
#pragma unroll
        for (int j = 0; j < 2; j++) {
            int idx = tid + j * 512;
            int row = idx >> 2, q = idx & 3;
            cp_async16(smb + stg * STAGE_BYTES + A_BYTES + row * B_STRIDE_B + q * 16,
                       g_W1f + row * C + kc * 32 + q * 8);
        }
    };

    {
        float4 p0[2], p1[2];
        ldA(0, p0);
        ldA(1, p1);
        cpB(0, 0); CP_COMMIT();
        cpB(1, 1); CP_COMMIT();
        stA(0, p0);
        stA(1, p1);
    }
    CP_WAIT1();
    __syncthreads();

    int g8 = lane >> 3, r8 = lane & 7;
    uint32_t aRel = (uint32_t)((wm * 32 + (g8 & 1) * 8 + r8) * A_STRIDE_B + (g8 >> 1) * 16);
    uint32_t bRel = (uint32_t)(A_BYTES + (wn * 64 + (g8 & 1) * 8 + r8) * B_STRIDE_B + (g8 >> 1) * 16);

    float acc[2][8][4];
#pragma unroll
    for (int mi = 0; mi < 2; mi++)
#pragma unroll
        for (int n8 = 0; n8 < 8; n8++)
#pragma unroll
            for (int e = 0; e < 4; e++) acc[mi][n8][e] = 0.f;

#pragma unroll
    for (int kc = 0; kc < 8; kc++) {
        int stg = kc % NSTAGE;
        int wstg = (kc + 2) % NSTAGE;

        float4 pf[2];
        if (kc < 6) {
            ldA(kc + 2, pf);
            cpB(kc + 2, wstg);
            CP_COMMIT();
        }

        uint32_t aB = smb + stg * STAGE_BYTES + aRel;
        uint32_t bB = smb + stg * STAGE_BYTES + bRel;
#pragma unroll
        for (int k16 = 0; k16 < 2; k16++) {
            uint32_t B[4][4];
#pragma unroll
            for (int nt = 0; nt < 4; nt++)
                ldm_x4(bB + nt * (16 * B_STRIDE_B) + k16 * 32, B[nt]);
            uint32_t A[2][4];
#pragma unroll
            for (int mi = 0; mi < 2; mi++)
                ldm_x4(aB + mi * (16 * A_STRIDE_B) + k16 * 32, A[mi]);
#pragma unroll
            for (int mi = 0; mi < 2; mi++)
#pragma unroll
                for (int n8 = 0; n8 < 8; n8++) {
                    int nt = n8 >> 1, sel = n8 & 1;
                    mma_f16(acc[mi][n8], A[mi], B[nt][sel], B[nt][sel + 2]);
                }
        }

        if (kc < 6) {
            stA(wstg, pf);
            if (kc < 5) CP_WAIT1(); else CP_WAIT0();
        }
        __syncthreads();
    }

    {
#pragma unroll
        for (int n8 = 0; n8 < 8; n8++) {
            float s0 = 0.f, s1 = 0.f, q0 = 0.f, q1 = 0.f;
#pragma unroll
            for (int mi = 0; mi < 2; mi++) {
                float e0 = acc[mi][n8][0], e1 = acc[mi][n8][1];
                float e2 = acc[mi][n8][2], e3 = acc[mi][n8][3];
                s0 += e0 + e2; s1 += e1 + e3;
                q0 += e0 * e0 + e2 * e2; q1 += e1 * e1 + e3 * e3;
            }
#pragma unroll
            for (int o = 4; o < 32; o <<= 1) {
                s0 += __shfl_xor_sync(0xffffffffu, s0, o);
                s1 += __shfl_xor_sync(0xffffffffu, s1, o);
                q0 += __shfl_xor_sync(0xffffffffu, q0, o);
                q1 += __shfl_xor_sync(0xffffffffu, q1, o);
            }
            if (lane < 4) {
                int col = wn * 64 + n8 * 8 + lane * 2;
                colsum[wm][col] = s0; colsum[wm][col + 1] = s1;
                colsq [wm][col] = q0; colsq [wm][col + 1] = q1;
            }
        }
    }

    __half* stage = (__half*)sm;
    __syncthreads();
#pragma unroll
    for (int mi = 0; mi < 2; mi++) {
        int row0 = wm * 32 + mi * 16 + (lane >> 2);
#pragma unroll
        for (int n8 = 0; n8 < 8; n8++) {
            int col = wn * 64 + n8 * 8 + (lane & 3) * 2;
            float2 bb = *(const float2*)&sbias[col];
            __half2 v01 = __floats2half2_rn(acc[mi][n8][0] + bb.x,
                                            acc[mi][n8][1] + bb.y);
            __half2 v23 = __floats2half2_rn(acc[mi][n8][2] + bb.x,
                                            acc[mi][n8][3] + bb.y);
            *(__half2*)&stage[row0 * STG_STRIDE + col] = v01;
            *(__half2*)&stage[(row0 + 8) * STG_STRIDE + col] = v23;
        }
    }
    __syncthreads();

    {
        size_t rowbase = (size_t)mb * 128;
#pragma unroll
        for (int it = 0; it < 8; it++) {
            int idx = tid + it * 512;
            int row = idx >> 5, ch = idx & 31;
            uint4 v = *(const uint4*)&stage[row * STG_STRIDE + ch * 8];
            *(uint4*)&g_h1f[(rowbase + row) * C + ch * 8] = v;
        }
        if (tid < 256) {
            float s = colsum[0][tid] + colsum[1][tid] + colsum[2][tid] + colsum[3][tid];
            float q = colsq[0][tid] + colsq[1][tid] + colsq[2][tid] + colsq[3][tid];
            g_psum[(size_t)tid * NMB + mb] = s;
            g_psq [(size_t)tid * NMB + mb] = q;
        }
    }
}

/* ================= stats: finalize bn coefficients (float4 reads) ========= */
__global__ void stats_kernel(const float* __restrict__ gamma, const float* __restrict__ beta,
                             const float* __restrict__ b1) {
    int c = blockIdx.x;
    int t = threadIdx.x;
    __shared__ float ss[256], sq[256];
    const float4* ps = (const float4*)(g_psum + (size_t)c * NMB);
    const float4* pq = (const float4*)(g_psq  + (size_t)c * NMB);
    float s = 0.f, q = 0.f;
#pragma unroll
    for (int i = 0; i < 2; i++) {
        float4 v = ps[t + i * 256];
        float4 w = pq[t + i * 256];
        s += v.x + v.y + v.z + v.w;
        q += w.x + w.y + w.z + w.w;
    }
    ss[t] = s; sq[t] = q;
    __syncthreads();
    for (int off = 128; off; off >>= 1) {
        if (t < off) { ss[t] += ss[t + off]; sq[t] += sq[t + off]; }
        __syncthreads();
    }
    if (t == 0) {
        float mraw = ss[0] / (float)NROWS;
        float var  = sq[0] / (float)NROWS - mraw * mraw;
        float mu   = mraw + b1[c];
        float rs   = rsqrtf(var + EPS);
        float a    = rs * gamma[c];
        g_bnA[c] = a;
        g_bnB[c] = beta[c] - mu * a;
    }
}

/* ================= kdot (exact R14 41us version) =================
   64-row tiles, 128 threads, 42KB smem -> 5 CTAs/SM. */
#define D_STRIDE_H 264
#define D_TILE (64 * D_STRIDE_H * 2)            /* 33792 */
#define D_A16_OFF D_TILE
#define D_DYN (D_A16_OFF + 16 * D_STRIDE_H * 2) /* 42240 */

__global__ __launch_bounds__(128, 5)
void kdot_kernel() {
    extern __shared__ char dynsm[];
    __shared__ float sA[C], sB_[C];
    __shared__ float cks[16];

    int t = threadIdx.x;
    int wid = t >> 5, lane = t & 31;
    int b = blockIdx.x;
    uint32_t smb = smem_u32(dynsm);

    {
        const __half* src = g_h1f + (size_t)b * 64 * C;
#pragma unroll
        for (int it = 0; it < 16; it++) {
            int idx = t + it * 128;
            int row = idx >> 5, cc = idx & 31;
            cp_async16(smb + row * (D_STRIDE_H * 2) + cc * 16,
                       src + row * C + cc * 8);
        }
#pragma unroll
        for (int it = 0; it < 4; it++) {
            int idx = t + it * 128;
            int row = idx >> 5, cc = idx & 31;
            cp_async16(smb + D_A16_OFF + row * (D_STRIDE_H * 2) + cc * 16,
                       g_A16 + row * C + cc * 8);
        }
        CP_COMMIT();
    }
    for (int i = t; i < C; i += 128) { sA[i] = g_bnA[i]; sB_[i] = g_bnB[i]; }
    if (t < 16) cks[t] = (t < 8) ? g_ckk[t] : g_cvv[t - 8];
    CP_WAIT0();
    __syncthreads();

#pragma unroll
    for (int it = 0; it < 16; it++) {
        int idx = t + it * 128;
        int row = idx >> 5, cc = idx & 31;
        uint32_t addr = row * (D_STRIDE_H * 2) + cc * 16;
        uint4 v = *(uint4*)(dynsm + addr);
        __half2* hp = (__half2*)&v;
        uint4 o4;
        __half2* op = (__half2*)&o4;
#pragma unroll
        for (int j = 0; j < 4; j++) {
            float2 f = __half22float2(hp[j]);
            float2 a2 = *(const float2*)&sA[cc * 8 + j * 2];
            float2 b2 = *(const float2*)&sB_[cc * 8 + j * 2];
            float h0 = fmaxf(fmaf(f.x, a2.x, b2.x), 0.f);
            float h1 = fmaxf(fmaf(f.y, a2.y, b2.y), 0.f);
            op[j] = __floats2half2_rn(h0, h1);
        }
        *(uint4*)(dynsm + addr) = o4;
    }
    __syncthreads();

    {
        int g8 = lane >> 3, r8 = lane & 7;
        uint32_t aBase = smb + (uint32_t)((wid * 16 + (g8 & 1) * 8 + r8) * (D_STRIDE_H * 2)
                                          + (g8 >> 1) * 16);
        uint32_t bBase = smb + D_A16_OFF
                       + (uint32_t)(((g8 & 1) * 8 + r8) * (D_STRIDE_H * 2) + (g8 >> 1) * 16);
        float a0[4] = {0.f, 0.f, 0.f, 0.f};
        float a1[4] = {0.f, 0.f, 0.f, 0.f};
#pragma unroll
        for (int k = 0; k < 16; k++) {
            uint32_t A[4], B[4];
            ldm_x4(aBase + k * 32, A);
            ldm_x4(bBase + k * 32, B);
            mma_f16(a0, A, B[0], B[2]);
            mma_f16(a1, A, B[1], B[3]);
        }
        int fr = lane >> 2, fc = (lane & 3) * 2;
        size_t r0 = (size_t)b * 64 + wid * 16 + fr;
        float* f0 = g_fin + r0 * 16;
        float* f1 = g_fin + (r0 + 8) * 16;
        f0[fc]         = a0[0] + cks[fc];
        f0[fc + 1]     = a0[1] + cks[fc + 1];
        f1[fc]         = a0[2] + cks[fc];
        f1[fc + 1]     = a0[3] + cks[fc + 1];
        f0[8 + fc]     = a1[0] + cks[8 + fc];
        f0[8 + fc + 1] = a1[1] + cks[8 + fc + 1];
        f1[8 + fc]     = a1[2] + cks[8 + fc];
        f1[8 + fc + 1] = a1[3] + cks[8 + fc + 1];
    }
}

/* ================= ksoft: per-graph softmax + tanh ================= */
__global__ __launch_bounds__(256, 4)
void ksoft_kernel(float* __restrict__ out) {
    __shared__ float sfin[128 * 17];
    __shared__ float hsum[H];
    int t = threadIdx.x;
    int wid = t >> 5, lane = t & 31;
    int g = blockIdx.x;

    const float* src = g_fin + (size_t)g * NPG * 16;
    for (int i = t; i < 128 * 16; i += 256) {
        int row = i >> 4, o = i & 15;
        sfin[row * 17 + o] = src[i];
    }
    __syncthreads();

    {
        int h = wid;
        float lv[4], tv[4];
        float m = -INFINITY;
#pragma unroll
        for (int k = 0; k < 4; k++) {
            int rr = lane + 32 * k;
            lv[k] = sfin[rr * 17 + h];
            tv[k] = sfin[rr * 17 + 8 + h];
            m = fmaxf(m, lv[k]);
        }
#pragma unroll
        for (int off = 16; off; off >>= 1)
            m = fmaxf(m, __shfl_xor_sync(0xffffffffu, m, off));
        float sp = 0.f, spt = 0.f;
#pragma unroll
        for (int k = 0; k < 4; k++) {
            float p = expf(lv[k] - m);
            sp  += p;
            spt += p * tv[k];
        }
#pragma unroll
        for (int off = 16; off; off >>= 1) {
            sp  += __shfl_xor_sync(0xffffffffu, sp,  off);
            spt += __shfl_xor_sync(0xffffffffu, spt, off);
        }
        if (lane == 0) hsum[h] = spt / sp;
    }
    __syncthreads();

    if (t == 0) {
        float s = g_cb;
#pragma unroll
        for (int h = 0; h < H; h++) s += hsum[h];
        out[g] = tanhf(s);
    }
}

/* ================= launch ================= */
extern "C" void kernel_launch(void* const* d_in, const int* in_sizes, int n_in,
                              void* d_out, int out_size) {
    const float* x     = (const float*)d_in[0];
    const float* W1    = (const float*)d_in[3];
    const float* b1    = (const float*)d_in[4];
    const float* gamma = (const float*)d_in[5];
    const float* beta  = (const float*)d_in[6];
    const float* W2    = (const float*)d_in[7];
    const float* b2    = (const float*)d_in[8];
    const float* Wq    = (const float*)d_in[9];
    const float* bq    = (const float*)d_in[10];
    const float* Wk    = (const float*)d_in[11];
    const float* bk    = (const float*)d_in[12];
    const float* Wv    = (const float*)d_in[13];
    const float* bv    = (const float*)d_in[14];
    const float* Wo    = (const float*)d_in[15];
    const float* bo    = (const float*)d_in[16];
    const float* Wr    = (const float*)d_in[17];
    const float* br    = (const float*)d_in[18];
    float* out = (float*)d_out;

    static int smem_set = 0;
    if (!smem_set) {
        cudaFuncSetAttribute(gemm1_mma, cudaFuncAttributeMaxDynamicSharedMemorySize,
                             SMEM_DYN);
        cudaFuncSetAttribute(kdot_kernel, cudaFuncAttributeMaxDynamicSharedMemorySize,
                             D_DYN);
        smem_set = 1;
    }

    prep_kernel<<<72, 256>>>(W1, Wq, bq, Wk, bk, Wv, bv, W2, b2, Wo, bo, Wr, br);
    gemm1_mma<<<NMB, 512, SMEM_DYN>>>(x, b1);
    stats_kernel<<<256, 256>>>(gamma, beta, b1);
    kdot_kernel<<<4096, 128, D_DYN>>>();
    ksoft_kernel<<<NGR, 256>>>(out);
}

// round 17
// speedup vs baseline: 1.1203x; 1.1203x over previous
#include <cuda_runtime.h>
#include <cuda_fp16.h>
#include <math.h>
#include <stdint.h>

#define NROWS 262144
#define C     256
#define NGR   2048
#define NPG   128
#define H     8
#define DH    32
#define EPS   1e-5f
#define ATT_SCALE 0.1767766952966369f   /* 1/sqrt(32) */
#define NMB   2048                      /* m-blocks of 128 rows */

/* ---------------- device scratch ---------------- */
__device__ __half g_h1f[(size_t)NROWS * C];        /* 134 MB */
__device__ __half g_W1f[C * C];
__device__ __half g_A16[16 * C];                   /* rows 0-7 Ak[h], 8-15 Av[h] */
__device__ float g_fin[(size_t)NROWS * 16];        /* 16.8 MB */
__device__ float g_psum[(size_t)C * NMB];
__device__ float g_psq [(size_t)C * NMB];
__device__ float g_bnA[C], g_bnB[C];
__device__ float g_ckk[H], g_cvv[H];
__device__ float g_cb;

/* ---------------- helpers ---------------- */
__device__ __forceinline__ uint32_t smem_u32(const void* p) {
    uint32_t a;
    asm("{ .reg .u64 t; cvta.to.shared.u64 t, %1; cvt.u32.u64 %0, t; }"
        : "=r"(a) : "l"(p));
    return a;
}
__device__ __forceinline__ void ldm_x4(uint32_t addr, uint32_t* r) {
    asm volatile("ldmatrix.sync.aligned.m8n8.x4.shared.b16 {%0,%1,%2,%3}, [%4];"
                 : "=r"(r[0]), "=r"(r[1]), "=r"(r[2]), "=r"(r[3]) : "r"(addr));
}
__device__ __forceinline__ void mma_f16(float* d, const uint32_t* a,
                                        uint32_t b0, uint32_t b1) {
    asm volatile(
        "mma.sync.aligned.m16n8k16.row.col.f32.f16.f16.f32 "
        "{%0,%1,%2,%3}, {%4,%5,%6,%7}, {%8,%9}, {%0,%1,%2,%3};"
        : "+f"(d[0]), "+f"(d[1]), "+f"(d[2]), "+f"(d[3])
        : "r"(a[0]), "r"(a[1]), "r"(a[2]), "r"(a[3]), "r"(b0), "r"(b1));
}
__device__ __forceinline__ void cp_async16(uint32_t dst, const void* src) {
    asm volatile("cp.async.cg.shared.global [%0], [%1], 16;"
                 :: "r"(dst), "l"(src) : "memory");
}
#define CP_COMMIT() asm volatile("cp.async.commit_group;" ::: "memory")
#define CP_WAIT0()  asm volatile("cp.async.wait_group 0;" ::: "memory")
#define CP_WAIT1()  asm volatile("cp.async.wait_group 1;" ::: "memory")

/* ================= prep_W1: W1 fp16 (blocks 0-63) + cb (block 64) ========= */
__global__ void prep_w1_kernel(const float* __restrict__ W1,
                               const float* __restrict__ Wr, const float* __restrict__ bo,
                               const float* __restrict__ br) {
    int t = threadIdx.x, b = blockIdx.x;
    if (b < 64) {
        int base = b * 1024;
#pragma unroll
        for (int k = 0; k < 4; k++) {
            int i = base + t + k * 256;
            g_W1f[i] = __float2half_rn(W1[i]);
        }
        return;
    }
    __shared__ float red[256];
    red[t] = Wr[t] * bo[t];
    __syncthreads();
    for (int off = 128; off; off >>= 1) {
        if (t < off) red[t] += red[t + off];
        __syncthreads();
    }
    if (t == 0) g_cb = red[0] + br[0];
}

/* ================= prep_heads: 32 blocks = 8 heads x 4 col groups ========= */
__global__ void prep_heads_kernel(const float* __restrict__ Wq, const float* __restrict__ bq,
                                  const float* __restrict__ Wk, const float* __restrict__ bk,
                                  const float* __restrict__ Wv, const float* __restrict__ bv,
                                  const float* __restrict__ W2, const float* __restrict__ b2,
                                  const float* __restrict__ Wo, const float* __restrict__ Wr) {
    int t = threadIdx.x;
    int h = blockIdx.x >> 2, cg = blockIdx.x & 3;
    int wid = t >> 5, lane = t & 31;
    __shared__ float qv[DH], uu[DH];
    __shared__ float skq[256], svu[256];
    __shared__ float part[2][256];      /* fold partials: [k/v][col64*4 + seg] */

    /* qv[d], uu[d] for this head (same on all 4 col-group blocks) */
#pragma unroll
    for (int r8i = 0; r8i < 8; r8i++) {
        int rr = wid * 8 + r8i;          /* 0..63 */
        float s = 0.f;
        if (rr < DH) {
            int row = h * DH + rr;
#pragma unroll
            for (int j = 0; j < 8; j++) s += Wq[row * C + lane + j * 32];
        } else {
            int e = h * DH + (rr - DH);
#pragma unroll
            for (int j = 0; j < 8; j++) {
                int c = lane + j * 32;
                s += Wr[c] * Wo[c * C + e];
            }
        }
#pragma unroll
        for (int o = 16; o; o >>= 1) s += __shfl_xor_sync(0xffffffffu, s, o);
        if (lane == 0) {
            if (rr < DH) qv[rr] = s + bq[h * DH + rr];
            else uu[rr - DH] = s;
        }
    }
    __syncthreads();

    /* skq/svu for all 256 a-columns (32-iter loop) */
    {
        float s = 0.f, s2 = 0.f;
#pragma unroll
        for (int d = 0; d < DH; d++) {
            s  += Wk[(h * DH + d) * C + t] * qv[d];
            s2 += uu[d] * Wv[(h * DH + d) * C + t];
        }
        skq[t] = s * ATT_SCALE;
        svu[t] = s2;
    }
    __syncthreads();

    /* fold W2 for 64 columns: col = cg*64 + (t&63); a-range (t>>6)*64 .. +64 */
    {
        int colL = t & 63, seg = t >> 6;
        int col = cg * 64 + colL;
        float sk = 0.f, sv = 0.f;
#pragma unroll 8
        for (int ai = 0; ai < 64; ai++) {
            int a = seg * 64 + ai;
            float w2 = W2[a * C + col];
            sk += skq[a] * w2;
            sv += svu[a] * w2;
        }
        part[0][colL * 4 + seg] = sk;
        part[1][colL * 4 + seg] = sv;
    }
    __syncthreads();
    if (t < 64) {
        int col = cg * 64 + t;
        float sk = part[0][t * 4] + part[0][t * 4 + 1] + part[0][t * 4 + 2] + part[0][t * 4 + 3];
        float sv = part[1][t * 4] + part[1][t * 4 + 1] + part[1][t * 4 + 2] + part[1][t * 4 + 3];
        g_A16[h * C + col]       = __float2half_rn(sk);
        g_A16[(8 + h) * C + col] = __float2half_rn(sv);
    }

    /* ckk/cvv: block cg==0 only (full 256-sum available in skq/svu) */
    if (cg == 0) {
        __shared__ float red[256], red2[256];
        float ckp = skq[t] * b2[t];
        float cvp = svu[t] * b2[t];
        if (t < DH) {
            ckp += bk[h * DH + t] * qv[t] * ATT_SCALE;
            cvp += uu[t] * bv[h * DH + t];
        }
        red[t] = ckp; red2[t] = cvp;
        __syncthreads();
        for (int off = 128; off; off >>= 1) {
            if (t < off) { red[t] += red[t + off]; red2[t] += red2[t + off]; }
            __syncthreads();
        }
        if (t == 0) { g_ckk[h] = red[0]; g_cvv[h] = red2[0]; }
    }
}

/* ================= GEMM1 (exact R7 166us version) ========================= */
#define A_STRIDE_B 80
#define B_STRIDE_B 80
#define A_BYTES (128 * A_STRIDE_B)
#define B_BYTES (256 * B_STRIDE_B)
#define STAGE_BYTES (A_BYTES + B_BYTES)
#define NSTAGE 3
#define STG_STRIDE 264
#define SMEM_DYN (NSTAGE * STAGE_BYTES)

__global__ __launch_bounds__(512, 1)
void gemm1_mma(const float* __restrict__ x, const float* __restrict__ b1) {
    extern __shared__ char sm[];
    __shared__ float sbias[256];
    __shared__ float colsum[4][256], colsq[4][256];

    int tid = threadIdx.x;
    int wid = tid >> 5, lane = tid & 31;
    int wm = wid >> 2, wn = wid & 3;
    int mb = blockIdx.x;
    uint32_t smb = smem_u32(sm);

    if (tid < 256) sbias[tid] = b1[tid];

    const float* xt = x + (size_t)mb * 128 * C;
    int arow = tid >> 2, af8 = tid & 3;

    auto ldA = [&](int kc, float4* pf) {
        const float* p = &xt[(size_t)arow * C + kc * 32 + af8 * 8];
        pf[0] = __ldg((const float4*)p);
        pf[1] = __ldg((const float4*)(p + 4));
    };
    auto stA = [&](int stg, const float4* pf) {
        __half h[8];
        h[0] = __float2half_rn(pf[0].x); h[1] = __float2half_rn(pf[0].y);
        h[2] = __float2half_rn(pf[0].z); h[3] = __float2half_rn(pf[0].w);
        h[4] = __float2half_rn(pf[1].x); h[5] = __float2half_rn(pf[1].y);
        h[6] = __float2half_rn(pf[1].z); h[7] = __float2half_rn(pf[1].w);
        *(uint4*)(sm + stg * STAGE_BYTES + arow * A_STRIDE_B + af8 * 16) = *(uint4*)h;
    };
    auto cpB = [&](int kc, int stg) {
#pragma unroll
        for (int j = 0; j < 2; j++) {
            int idx = tid + j * 512;
            int row = idx >> 2, q = idx & 3;
            cp_async16(smb + stg * STAGE_BYTES + A_BYTES + row * B_STRIDE_B + q * 16,
                       g_W1f + row * C + kc * 32 + q * 8);
        }
    };

    {
        float4 p0[2], p1[2];
        ldA(0, p0);
        ldA(1, p1);
        cpB(0, 0); CP_COMMIT();
        cpB(1, 1); CP_COMMIT();
        stA(0, p0);
        stA(1, p1);
    }
    CP_WAIT1();
    __syncthreads();

    int g8 = lane >> 3, r8 = lane & 7;
    uint32_t aRel = (uint32_t)((wm * 32 + (g8 & 1) * 8 + r8) * A_STRIDE_B + (g8 >> 1) * 16);
    uint32_t bRel = (uint32_t)(A_BYTES + (wn * 64 + (g8 & 1) * 8 + r8) * B_STRIDE_B + (g8 >> 1) * 16);

    float acc[2][8][4];
#pragma unroll
    for (int mi = 0; mi < 2; mi++)
#pragma unroll
        for (int n8 = 0; n8 < 8; n8++)
#pragma unroll
            for (int e = 0; e < 4; e++) acc[mi][n8][e] = 0.f;

#pragma unroll
    for (int kc = 0; kc < 8; kc++) {
        int stg = kc % NSTAGE;
        int wstg = (kc + 2) % NSTAGE;

        float4 pf[2];
        if (kc < 6) {
            ldA(kc + 2, pf);
            cpB(kc + 2, wstg);
            CP_COMMIT();
        }

        uint32_t aB = smb + stg * STAGE_BYTES + aRel;
        uint32_t bB = smb + stg * STAGE_BYTES + bRel;
#pragma unroll
        for (int k16 = 0; k16 < 2; k16++) {
            uint32_t B[4][4];
#pragma unroll
            for (int nt = 0; nt < 4; nt++)
                ldm_x4(bB + nt * (16 * B_STRIDE_B) + k16 * 32, B[nt]);
            uint32_t A[2][4];
#pragma unroll
            for (int mi = 0; mi < 2; mi++)
                ldm_x4(aB + mi * (16 * A_STRIDE_B) + k16 * 32, A[mi]);
#pragma unroll
            for (int mi = 0; mi < 2; mi++)
#pragma unroll
                for (int n8 = 0; n8 < 8; n8++) {
                    int nt = n8 >> 1, sel = n8 & 1;
                    mma_f16(acc[mi][n8], A[mi], B[nt][sel], B[nt][sel + 2]);
                }
        }

        if (kc < 6) {
            stA(wstg, pf);
            if (kc < 5) CP_WAIT1(); else CP_WAIT0();
        }
        __syncthreads();
    }

    {
#pragma unroll
        for (int n8 = 0; n8 < 8; n8++) {
            float s0 = 0.f, s1 = 0.f, q0 = 0.f, q1 = 0.f;
#pragma unroll
            for (int mi = 0; mi < 2; mi++) {
                float e0 = acc[mi][n8][0], e1 = acc[mi][n8][1];
                float e2 = acc[mi][n8][2], e3 = acc[mi][n8][3];
                s0 += e0 + e2; s1 += e1 + e3;
                q0 += e0 * e0 + e2 * e2; q1 += e1 * e1 + e3 * e3;
            }
#pragma unroll
            for (int o = 4; o < 32; o <<= 1) {
                s0 += __shfl_xor_sync(0xffffffffu, s0, o);
                s1 += __shfl_xor_sync(0xffffffffu, s1, o);
                q0 += __shfl_xor_sync(0xffffffffu, q0, o);
                q1 += __shfl_xor_sync(0xffffffffu, q1, o);
            }
            if (lane < 4) {
                int col = wn * 64 + n8 * 8 + lane * 2;
                colsum[wm][col] = s0; colsum[wm][col + 1] = s1;
                colsq [wm][col] = q0; colsq [wm][col + 1] = q1;
            }
        }
    }

    __half* stage = (__half*)sm;
    __syncthreads();
#pragma unroll
    for (int mi = 0; mi < 2; mi++) {
        int row0 = wm * 32 + mi * 16 + (lane >> 2);
#pragma unroll
        for (int n8 = 0; n8 < 8; n8++) {
            int col = wn * 64 + n8 * 8 + (lane & 3) * 2;
            float2 bb = *(const float2*)&sbias[col];
            __half2 v01 = __floats2half2_rn(acc[mi][n8][0] + bb.x,
                                            acc[mi][n8][1] + bb.y);
            __half2 v23 = __floats2half2_rn(acc[mi][n8][2] + bb.x,
                                            acc[mi][n8][3] + bb.y);
            *(__half2*)&stage[row0 * STG_STRIDE + col] = v01;
            *(__half2*)&stage[(row0 + 8) * STG_STRIDE + col] = v23;
        }
    }
    __syncthreads();

    {
        size_t rowbase = (size_t)mb * 128;
#pragma unroll
        for (int it = 0; it < 8; it++) {
            int idx = tid + it * 512;
            int row = idx >> 5, ch = idx & 31;
            uint4 v = *(const uint4*)&stage[row * STG_STRIDE + ch * 8];
            *(uint4*)&g_h1f[(rowbase + row) * C + ch * 8] = v;
        }
        if (tid < 256) {
            float s = colsum[0][tid] + colsum[1][tid] + colsum[2][tid] + colsum[3][tid];
            float q = colsq[0][tid] + colsq[1][tid] + colsq[2][tid] + colsq[3][tid];
            g_psum[(size_t)tid * NMB + mb] = s;
            g_psq [(size_t)tid * NMB + mb] = q;
        }
    }
}

/* ================= stats: finalize bn coefficients (float4 reads) ========= */
__global__ void stats_kernel(const float* __restrict__ gamma, const float* __restrict__ beta,
                             const float* __restrict__ b1) {
    int c = blockIdx.x;
    int t = threadIdx.x;
    __shared__ float ss[256], sq[256];
    const float4* ps = (const float4*)(g_psum + (size_t)c * NMB);
    const float4* pq = (const float4*)(g_psq  + (size_t)c * NMB);
    float s = 0.f, q = 0.f;
#pragma unroll
    for (int i = 0; i < 2; i++) {
        float4 v = ps[t + i * 256];
        float4 w = pq[t + i * 256];
        s += v.x + v.y + v.z + v.w;
        q += w.x + w.y + w.z + w.w;
    }
    ss[t] = s; sq[t] = q;
    __syncthreads();
    for (int off = 128; off; off >>= 1) {
        if (t < off) { ss[t] += ss[t + off]; sq[t] += sq[t + off]; }
        __syncthreads();
    }
    if (t == 0) {
        float mraw = ss[0] / (float)NROWS;
        float var  = sq[0] / (float)NROWS - mraw * mraw;
        float mu   = mraw + b1[c];
        float rs   = rsqrtf(var + EPS);
        float a    = rs * gamma[c];
        g_bnA[c] = a;
        g_bnB[c] = beta[c] - mu * a;
    }
}

/* ================= kdot (exact R14 41us version) ================= */
#define D_STRIDE_H 264
#define D_TILE (64 * D_STRIDE_H * 2)            /* 33792 */
#define D_A16_OFF D_TILE
#define D_DYN (D_A16_OFF + 16 * D_STRIDE_H * 2) /* 42240 */

__global__ __launch_bounds__(128, 5)
void kdot_kernel() {
    extern __shared__ char dynsm[];
    __shared__ float sA[C], sB_[C];
    __shared__ float cks[16];

    int t = threadIdx.x;
    int wid = t >> 5, lane = t & 31;
    int b = blockIdx.x;
    uint32_t smb = smem_u32(dynsm);

    {
        const __half* src = g_h1f + (size_t)b * 64 * C;
#pragma unroll
        for (int it = 0; it < 16; it++) {
            int idx = t + it * 128;
            int row = idx >> 5, cc = idx & 31;
            cp_async16(smb + row * (D_STRIDE_H * 2) + cc * 16,
                       src + row * C + cc * 8);
        }
#pragma unroll
        for (int it = 0; it < 4; it++) {
            int idx = t + it * 128;
            int row = idx >> 5, cc = idx & 31;
            cp_async16(smb + D_A16_OFF + row * (D_STRIDE_H * 2) + cc * 16,
                       g_A16 + row * C + cc * 8);
        }
        CP_COMMIT();
    }
    for (int i = t; i < C; i += 128) { sA[i] = g_bnA[i]; sB_[i] = g_bnB[i]; }
    if (t < 16) cks[t] = (t < 8) ? g_ckk[t] : g_cvv[t - 8];
    CP_WAIT0();
    __syncthreads();

#pragma unroll
    for (int it = 0; it < 16; it++) {
        int idx = t + it * 128;
        int row = idx >> 5, cc = idx & 31;
        uint32_t addr = row * (D_STRIDE_H * 2) + cc * 16;
        uint4 v = *(uint4*)(dynsm + addr);
        __half2* hp = (__half2*)&v;
        uint4 o4;
        __half2* op = (__half2*)&o4;
#pragma unroll
        for (int j = 0; j < 4; j++) {
            float2 f = __half22float2(hp[j]);
            float2 a2 = *(const float2*)&sA[cc * 8 + j * 2];
            float2 b2 = *(const float2*)&sB_[cc * 8 + j * 2];
            float h0 = fmaxf(fmaf(f.x, a2.x, b2.x), 0.f);
            float h1 = fmaxf(fmaf(f.y, a2.y, b2.y), 0.f);
            op[j] = __floats2half2_rn(h0, h1);
        }
        *(uint4*)(dynsm + addr) = o4;
    }
    __syncthreads();

    {
        int g8 = lane >> 3, r8 = lane & 7;
        uint32_t aBase = smb + (uint32_t)((wid * 16 + (g8 & 1) * 8 + r8) * (D_STRIDE_H * 2)
                                          + (g8 >> 1) * 16);
        uint32_t bBase = smb + D_A16_OFF
                       + (uint32_t)(((g8 & 1) * 8 + r8) * (D_STRIDE_H * 2) + (g8 >> 1) * 16);
        float a0[4] = {0.f, 0.f, 0.f, 0.f};
        float a1[4] = {0.f, 0.f, 0.f, 0.f};
#pragma unroll
        for (int k = 0; k < 16; k++) {
            uint32_t A[4], B[4];
            ldm_x4(aBase + k * 32, A);
            ldm_x4(bBase + k * 32, B);
            mma_f16(a0, A, B[0], B[2]);
            mma_f16(a1, A, B[1], B[3]);
        }
        int fr = lane >> 2, fc = (lane & 3) * 2;
        size_t r0 = (size_t)b * 64 + wid * 16 + fr;
        float* f0 = g_fin + r0 * 16;
        float* f1 = g_fin + (r0 + 8) * 16;
        f0[fc]         = a0[0] + cks[fc];
        f0[fc + 1]     = a0[1] + cks[fc + 1];
        f1[fc]         = a0[2] + cks[fc];
        f1[fc + 1]     = a0[3] + cks[fc + 1];
        f0[8 + fc]     = a1[0] + cks[8 + fc];
        f0[8 + fc + 1] = a1[1] + cks[8 + fc + 1];
        f1[8 + fc]     = a1[2] + cks[8 + fc];
        f1[8 + fc + 1] = a1[3] + cks[8 + fc + 1];
    }
}

/* ================= ksoft: per-graph softmax + tanh ================= */
__global__ __launch_bounds__(256, 4)
void ksoft_kernel(float* __restrict__ out) {
    __shared__ float sfin[128 * 17];
    __shared__ float hsum[H];
    int t = threadIdx.x;
    int wid = t >> 5, lane = t & 31;
    int g = blockIdx.x;

    const float* src = g_fin + (size_t)g * NPG * 16;
    for (int i = t; i < 128 * 16; i += 256) {
        int row = i >> 4, o = i & 15;
        sfin[row * 17 + o] = src[i];
    }
    __syncthreads();

    {
        int h = wid;
        float lv[4], tv[4];
        float m = -INFINITY;
#pragma unroll
        for (int k = 0; k < 4; k++) {
            int rr = lane + 32 * k;
            lv[k] = sfin[rr * 17 + h];
            tv[k] = sfin[rr * 17 + 8 + h];
            m = fmaxf(m, lv[k]);
        }
#pragma unroll
        for (int off = 16; off; off >>= 1)
            m = fmaxf(m, __shfl_xor_sync(0xffffffffu, m, off));
        float sp = 0.f, spt = 0.f;
#pragma unroll
        for (int k = 0; k < 4; k++) {
            float p = expf(lv[k] - m);
            sp  += p;
            spt += p * tv[k];
        }
#pragma unroll
        for (int off = 16; off; off >>= 1) {
            sp  += __shfl_xor_sync(0xffffffffu, sp,  off);
            spt += __shfl_xor_sync(0xffffffffu, spt, off);
        }
        if (lane == 0) hsum[h] = spt / sp;
    }
    __syncthreads();

    if (t == 0) {
        float s = g_cb;
#pragma unroll
        for (int h = 0; h < H; h++) s += hsum[h];
        out[g] = tanhf(s);
    }
}

/* ================= launch ================= */
extern "C" void kernel_launch(void* const* d_in, const int* in_sizes, int n_in,
                              void* d_out, int out_size) {
    const float* x     = (const float*)d_in[0];
    const float* W1    = (const float*)d_in[3];
    const float* b1    = (const float*)d_in[4];
    const float* gamma = (const float*)d_in[5];
    const float* beta  = (const float*)d_in[6];
    const float* W2    = (const float*)d_in[7];
    const float* b2    = (const float*)d_in[8];
    const float* Wq    = (const float*)d_in[9];
    const float* bq    = (const float*)d_in[10];
    const float* Wk    = (const float*)d_in[11];
    const float* bk    = (const float*)d_in[12];
    const float* Wv    = (const float*)d_in[13];
    const float* bv    = (const float*)d_in[14];
    const float* Wo    = (const float*)d_in[15];
    const float* bo    = (const float*)d_in[16];
    const float* Wr    = (const float*)d_in[17];
    const float* br    = (const float*)d_in[18];
    float* out = (float*)d_out;

    static int smem_set = 0;
    if (!smem_set) {
        cudaFuncSetAttribute(gemm1_mma, cudaFuncAttributeMaxDynamicSharedMemorySize,
                             SMEM_DYN);
        cudaFuncSetAttribute(kdot_kernel, cudaFuncAttributeMaxDynamicSharedMemorySize,
                             D_DYN);
        smem_set = 1;
    }

    prep_w1_kernel<<<65, 256>>>(W1, Wr, bo, br);
    gemm1_mma<<<NMB, 512, SMEM_DYN>>>(x, b1);
    prep_heads_kernel<<<32, 256>>>(Wq, bq, Wk, bk, Wv, bv, W2, b2, Wo, Wr);
    stats_kernel<<<256, 256>>>(gamma, beta, b1);
    kdot_kernel<<<4096, 128, D_DYN>>>();
    ksoft_kernel<<<NGR, 256>>>(out);
}